// round 2
// baseline (speedup 1.0000x reference)
#include <cuda_runtime.h>
#include <math.h>

#define BSZ 4096
#define TT  24
#define HID 1024
#define H3  3072
#define KP  1040   // 1024 (h) + 1 (dec) + 12 (aux) + 1 (bias) + 2 pad
#define ROWS_PER_CTA 16

// Scratch (device globals — allowed; no cudaMalloc anywhere)
__device__ float g_A[BSZ * KP];      // [h | dec | aux | 1 | 0 0] per row
__device__ float g_gates[BSZ * H3];  // GEMM output: [r | z | h_n]
__device__ float g_W[H3 * KP];       // combined weight (built per launch)
__device__ float g_cur[BSZ];         // previous step's out
__device__ float g_loss;             // loss accumulator

__device__ __forceinline__ float sigmoidf_(float x) { return 1.0f / (1.0f + expf(-x)); }

// ---------------------------------------------------------------------------
// Init: h <- hn, cur <- current_pm25, loss <- 0
// ---------------------------------------------------------------------------
__global__ void k_init(const float* __restrict__ hn, const float* __restrict__ cur_pm) {
    int row = blockIdx.x;
    for (int j = threadIdx.x; j < HID; j += blockDim.x)
        g_A[row * KP + j] = hn[row * HID + j];
    if (threadIdx.x == 0) {
        g_A[row * KP + 1038] = 0.0f;
        g_A[row * KP + 1039] = 0.0f;
        g_cur[row] = cur_pm[row];
        if (row == 0) g_loss = 0.0f;
    }
}

// ---------------------------------------------------------------------------
// Build combined weight matrix  g_W[c][k]:
//   k < 1024           : W_hh[c][k]
//   c < 2048 (r,z):
//     k in [1024,1036] : W_ih[c][k-1024]   (dec col + 12 aux cols)
//     k == 1037        : b_ih[c] + b_hh[c]
//   c >= 2048 (h_n):
//     k == 1037        : b_hh[c]           (x-side of n handled separately)
//   else 0
// ---------------------------------------------------------------------------
__global__ void k_wbig(const float* __restrict__ W_hh, const float* __restrict__ W_ih,
                       const float* __restrict__ b_ih, const float* __restrict__ b_hh) {
    int idx = blockIdx.x * blockDim.x + threadIdx.x;
    int total = H3 * KP;
    for (; idx < total; idx += gridDim.x * blockDim.x) {
        int c = idx / KP;
        int k = idx - c * KP;
        float val;
        if (k < 1024) {
            val = W_hh[c * 1024 + k];
        } else if (c < 2048) {
            if (k <= 1036)       val = W_ih[c * 13 + (k - 1024)];
            else if (k == 1037)  val = b_ih[c] + b_hh[c];
            else                 val = 0.0f;
        } else {
            val = (k == 1037) ? b_hh[c] : 0.0f;
        }
        g_W[idx] = val;
    }
}

// ---------------------------------------------------------------------------
// Per-step x-fill: A[row][1024..1037] = [dec, aux*12, 1]
// ---------------------------------------------------------------------------
__global__ void k_xfill(const float* __restrict__ aux, const float* __restrict__ tgt_seq,
                        const float* __restrict__ v, int t) {
    int row = blockIdx.x * blockDim.x + threadIdx.x;
    if (row >= BSZ) return;
    float dec;
    if (t == 0) {
        dec = g_cur[row];
    } else {
        float tg = tgt_seq[row * TT + (t - 1)];
        float m = (tg != 0.0f) ? v[row * TT + t] : 0.0f;
        dec = (m == 1.0f) ? tg : g_cur[row];
    }
    float* Ar = &g_A[row * KP];
    Ar[1024] = dec;
#pragma unroll
    for (int f = 0; f < 12; f++)
        Ar[1025 + f] = aux[(row * TT + t) * 12 + f];
    Ar[1037] = 1.0f;
}

// ---------------------------------------------------------------------------
// fp32 SIMT GEMM: gates[m][n] = sum_k A[m][k] * W[n][k]
// 128x128 tile, BK=8, 256 threads, 8x8 per-thread microtile
// ---------------------------------------------------------------------------
__global__ void __launch_bounds__(256) k_gemm() {
    __shared__ float As[8][128];
    __shared__ float Bs[8][128];

    int bm = blockIdx.y * 128;
    int bn = blockIdx.x * 128;
    int tid = threadIdx.x;
    int lr = tid >> 1;
    int lc = (tid & 1) * 4;

    const float* Aptr = &g_A[(bm + lr) * KP + lc];
    const float* Bptr = &g_W[(bn + lr) * KP + lc];

    float acc[8][8];
#pragma unroll
    for (int i = 0; i < 8; i++)
#pragma unroll
        for (int j = 0; j < 8; j++) acc[i][j] = 0.0f;

    int tm = (tid >> 4) * 8;
    int tn = (tid & 15) * 8;

    for (int k0 = 0; k0 < KP; k0 += 8) {
        float4 av = *(const float4*)(Aptr + k0);
        float4 bv = *(const float4*)(Bptr + k0);
        __syncthreads();
        As[lc + 0][lr] = av.x; As[lc + 1][lr] = av.y;
        As[lc + 2][lr] = av.z; As[lc + 3][lr] = av.w;
        Bs[lc + 0][lr] = bv.x; Bs[lc + 1][lr] = bv.y;
        Bs[lc + 2][lr] = bv.z; Bs[lc + 3][lr] = bv.w;
        __syncthreads();
#pragma unroll
        for (int k = 0; k < 8; k++) {
            float4 a0 = *(const float4*)&As[k][tm];
            float4 a1 = *(const float4*)&As[k][tm + 4];
            float4 b0 = *(const float4*)&Bs[k][tn];
            float4 b1 = *(const float4*)&Bs[k][tn + 4];
            float ar[8] = {a0.x, a0.y, a0.z, a0.w, a1.x, a1.y, a1.z, a1.w};
            float br[8] = {b0.x, b0.y, b0.z, b0.w, b1.x, b1.y, b1.z, b1.w};
#pragma unroll
            for (int i = 0; i < 8; i++)
#pragma unroll
                for (int j = 0; j < 8; j++)
                    acc[i][j] = fmaf(ar[i], br[j], acc[i][j]);
        }
    }
#pragma unroll
    for (int i = 0; i < 8; i++) {
        float* Cp = &g_gates[(bm + tm + i) * H3 + bn + tn];
        *(float4*)(Cp + 0) = make_float4(acc[i][0], acc[i][1], acc[i][2], acc[i][3]);
        *(float4*)(Cp + 4) = make_float4(acc[i][4], acc[i][5], acc[i][6], acc[i][7]);
    }
}

// ---------------------------------------------------------------------------
// GRU elementwise + i_n recompute + per-row reductions (logits, out, loss)
// One CTA handles ROWS_PER_CTA rows. Dynamic smem: W_ih n-gate rows + b_ih.
//   sw[j*14 + 0]      = b_ih[2048+j]
//   sw[j*14 + 1 + f]  = W_ih[(2048+j)*13 + f]   (f=0: dec col, f=1..12: aux)
// ---------------------------------------------------------------------------
__global__ void __launch_bounds__(256) k_gru(
    const float* __restrict__ W_ih, const float* __restrict__ b_ih,
    const float* __restrict__ emb, const float* __restrict__ W_out,
    const float* __restrict__ b_out, const int* __restrict__ st,
    float* __restrict__ outp, int t)
{
    extern __shared__ float sw[];  // 1024*14 floats = 57344 B
    __shared__ float red[8][6];
    int tid = threadIdx.x;

    for (int idx = tid; idx < HID * 14; idx += 256) {
        int j = idx / 14;
        int c = idx - j * 14;
        sw[idx] = (c == 0) ? b_ih[2048 + j] : W_ih[(2048 + j) * 13 + (c - 1)];
    }
    __syncthreads();

    float loss_local = 0.0f;
    float bout = b_out[0];

    for (int rr = 0; rr < ROWS_PER_CTA; rr++) {
        int row = blockIdx.x * ROWS_PER_CTA + rr;
        const float* Ar = &g_A[row * KP];
        float dec = Ar[1024];
        float ax[12];
#pragma unroll
        for (int f = 0; f < 12; f++) ax[f] = Ar[1025 + f];

        float e0 = 0.f, e1 = 0.f, e2 = 0.f, e3 = 0.f, e4 = 0.f, od = 0.f;
        const float* gr = &g_gates[row * H3];

        for (int j = tid; j < HID; j += 256) {
            float r = sigmoidf_(gr[j]);
            float z = sigmoidf_(gr[1024 + j]);
            const float* w = &sw[j * 14];
            float in_ = fmaf(dec, w[1], w[0]);
#pragma unroll
            for (int f = 0; f < 12; f++) in_ = fmaf(ax[f], w[2 + f], in_);
            float n = tanhf(fmaf(r, gr[2048 + j], in_));
            float hp = g_A[row * KP + j];
            float h = (1.0f - z) * n + z * hp;
            g_A[row * KP + j] = h;
            e0 = fmaf(h, emb[0 * HID + j], e0);
            e1 = fmaf(h, emb[1 * HID + j], e1);
            e2 = fmaf(h, emb[2 * HID + j], e2);
            e3 = fmaf(h, emb[3 * HID + j], e3);
            e4 = fmaf(h, emb[4 * HID + j], e4);
            od = fmaf(h, W_out[j], od);
        }

        float vals[6] = {e0, e1, e2, e3, e4, od};
#pragma unroll
        for (int s = 16; s > 0; s >>= 1)
#pragma unroll
            for (int vv = 0; vv < 6; vv++)
                vals[vv] += __shfl_down_sync(0xffffffffu, vals[vv], s);
        if ((tid & 31) == 0)
#pragma unroll
            for (int vv = 0; vv < 6; vv++) red[tid >> 5][vv] = vals[vv];
        __syncthreads();
        if (tid == 0) {
            float l[6];
#pragma unroll
            for (int vv = 0; vv < 6; vv++) {
                float s = 0.f;
#pragma unroll
                for (int w8 = 0; w8 < 8; w8++) s += red[w8][vv];
                l[vv] = s;
            }
            float mx = l[0];
#pragma unroll
            for (int k2 = 1; k2 < 5; k2++) mx = fmaxf(mx, l[k2]);
            float se = 0.f;
#pragma unroll
            for (int k2 = 0; k2 < 5; k2++) se += expf(l[k2] - mx);
            float lse = mx + logf(se);
            int pos = st[row * TT + t];
            loss_local += lse - l[pos];
            float o = l[5] + bout;
            g_cur[row] = o;
            outp[row * TT + t] = o;
        }
        __syncthreads();
    }
    if (tid == 0) atomicAdd(&g_loss, loss_local);
}

// ---------------------------------------------------------------------------
__global__ void k_final(float* outp, int out_size) {
    if (out_size > BSZ * TT)
        outp[BSZ * TT] = g_loss * (1.0f / ((float)BSZ * (float)TT));
}

// ---------------------------------------------------------------------------
extern "C" void kernel_launch(void* const* d_in, const int* in_sizes, int n_in,
                              void* d_out, int out_size) {
    const float* aux    = (const float*)d_in[0];
    const float* cur_pm = (const float*)d_in[1];
    const float* hn     = (const float*)d_in[2];
    const int*   st     = (const int*)  d_in[3];
    const float* tgt    = (const float*)d_in[4];
    const float* v      = (const float*)d_in[5];
    const float* W_ih   = (const float*)d_in[6];
    const float* W_hh   = (const float*)d_in[7];
    const float* b_ih   = (const float*)d_in[8];
    const float* b_hh   = (const float*)d_in[9];
    const float* emb    = (const float*)d_in[10];
    const float* W_out  = (const float*)d_in[11];
    const float* b_out  = (const float*)d_in[12];
    float* outp = (float*)d_out;

    cudaFuncSetAttribute(k_gru, cudaFuncAttributeMaxDynamicSharedMemorySize, 14 * HID * 4);

    k_init<<<BSZ, 256>>>(hn, cur_pm);
    k_wbig<<<2048, 256>>>(W_hh, W_ih, b_ih, b_hh);

    dim3 gg(H3 / 128, BSZ / 128);
    for (int t = 0; t < TT; t++) {
        k_xfill<<<(BSZ + 255) / 256, 256>>>(aux, tgt, v, t);
        k_gemm<<<gg, 256>>>();
        k_gru<<<BSZ / ROWS_PER_CTA, 256, 14 * HID * 4>>>(W_ih, b_ih, emb, W_out, b_out, st, outp, t);
    }
    k_final<<<1, 1>>>(outp, out_size);
}

// round 4
// speedup vs baseline: 1.0009x; 1.0009x over previous
#include <cuda_runtime.h>
#include <math.h>

#define BSZ 4096
#define TT  24
#define HID 1024
#define H3  3072
#define KP  1040   // 1024 (h) + 1 (dec) + 12 (aux) + 1 (bias) + 2 pad
#define ROWS_PER_CTA 16

// Scratch (device globals — allowed; no cudaMalloc anywhere)
__device__ float g_A[BSZ * KP];      // [h | dec | aux | 1 | 0 0] per row
__device__ float g_gates[BSZ * H3];  // GEMM output: [r | z | h_n]
__device__ float g_W[H3 * KP];       // combined weight (built per launch)
__device__ float g_cur[BSZ];         // previous step's out
__device__ float g_loss;             // loss accumulator

__device__ __forceinline__ float sigmoidf_(float x) { return 1.0f / (1.0f + expf(-x)); }

// ---------------------------------------------------------------------------
// Init: h <- hn, cur <- current_pm25, loss <- 0
// ---------------------------------------------------------------------------
__global__ void k_init(const float* __restrict__ hn, const float* __restrict__ cur_pm) {
    int row = blockIdx.x;
    for (int j = threadIdx.x; j < HID; j += blockDim.x)
        g_A[row * KP + j] = hn[row * HID + j];
    if (threadIdx.x == 0) {
        g_A[row * KP + 1038] = 0.0f;
        g_A[row * KP + 1039] = 0.0f;
        g_cur[row] = cur_pm[row];
        if (row == 0) g_loss = 0.0f;
    }
}

// ---------------------------------------------------------------------------
// Build combined weight matrix  g_W[c][k]:
//   k < 1024           : W_hh[c][k]
//   c < 2048 (r,z):
//     k in [1024,1036] : W_ih[c][k-1024]   (dec col + 12 aux cols)
//     k == 1037        : b_ih[c] + b_hh[c]
//   c >= 2048 (h_n):
//     k == 1037        : b_hh[c]           (x-side of n handled separately)
//   else 0
// ---------------------------------------------------------------------------
__global__ void k_wbig(const float* __restrict__ W_hh, const float* __restrict__ W_ih,
                       const float* __restrict__ b_ih, const float* __restrict__ b_hh) {
    int idx = blockIdx.x * blockDim.x + threadIdx.x;
    int total = H3 * KP;
    for (; idx < total; idx += gridDim.x * blockDim.x) {
        int c = idx / KP;
        int k = idx - c * KP;
        float val;
        if (k < 1024) {
            val = W_hh[c * 1024 + k];
        } else if (c < 2048) {
            if (k <= 1036)       val = W_ih[c * 13 + (k - 1024)];
            else if (k == 1037)  val = b_ih[c] + b_hh[c];
            else                 val = 0.0f;
        } else {
            val = (k == 1037) ? b_hh[c] : 0.0f;
        }
        g_W[idx] = val;
    }
}

// ---------------------------------------------------------------------------
// Per-step x-fill: A[row][1024..1037] = [dec, aux*12, 1]
// ---------------------------------------------------------------------------
__global__ void k_xfill(const float* __restrict__ aux, const float* __restrict__ tgt_seq,
                        const float* __restrict__ v, int t) {
    int row = blockIdx.x * blockDim.x + threadIdx.x;
    if (row >= BSZ) return;
    float dec;
    if (t == 0) {
        dec = g_cur[row];
    } else {
        float tg = tgt_seq[row * TT + (t - 1)];
        float m = (tg != 0.0f) ? v[row * TT + t] : 0.0f;
        dec = (m == 1.0f) ? tg : g_cur[row];
    }
    float* Ar = &g_A[row * KP];
    Ar[1024] = dec;
#pragma unroll
    for (int f = 0; f < 12; f++)
        Ar[1025 + f] = aux[(row * TT + t) * 12 + f];
    Ar[1037] = 1.0f;
}

// ---------------------------------------------------------------------------
// fp32 SIMT GEMM: gates[m][n] = sum_k A[m][k] * W[n][k]
// 128x128 tile, BK=8, 256 threads, 8x8 per-thread microtile
// ---------------------------------------------------------------------------
__global__ void __launch_bounds__(256) k_gemm() {
    __shared__ float As[8][128];
    __shared__ float Bs[8][128];

    int bm = blockIdx.y * 128;
    int bn = blockIdx.x * 128;
    int tid = threadIdx.x;
    int lr = tid >> 1;
    int lc = (tid & 1) * 4;

    const float* Aptr = &g_A[(bm + lr) * KP + lc];
    const float* Bptr = &g_W[(bn + lr) * KP + lc];

    float acc[8][8];
#pragma unroll
    for (int i = 0; i < 8; i++)
#pragma unroll
        for (int j = 0; j < 8; j++) acc[i][j] = 0.0f;

    int tm = (tid >> 4) * 8;
    int tn = (tid & 15) * 8;

    for (int k0 = 0; k0 < KP; k0 += 8) {
        float4 av = *(const float4*)(Aptr + k0);
        float4 bv = *(const float4*)(Bptr + k0);
        __syncthreads();
        As[lc + 0][lr] = av.x; As[lc + 1][lr] = av.y;
        As[lc + 2][lr] = av.z; As[lc + 3][lr] = av.w;
        Bs[lc + 0][lr] = bv.x; Bs[lc + 1][lr] = bv.y;
        Bs[lc + 2][lr] = bv.z; Bs[lc + 3][lr] = bv.w;
        __syncthreads();
#pragma unroll
        for (int k = 0; k < 8; k++) {
            float4 a0 = *(const float4*)&As[k][tm];
            float4 a1 = *(const float4*)&As[k][tm + 4];
            float4 b0 = *(const float4*)&Bs[k][tn];
            float4 b1 = *(const float4*)&Bs[k][tn + 4];
            float ar[8] = {a0.x, a0.y, a0.z, a0.w, a1.x, a1.y, a1.z, a1.w};
            float br[8] = {b0.x, b0.y, b0.z, b0.w, b1.x, b1.y, b1.z, b1.w};
#pragma unroll
            for (int i = 0; i < 8; i++)
#pragma unroll
                for (int j = 0; j < 8; j++)
                    acc[i][j] = fmaf(ar[i], br[j], acc[i][j]);
        }
    }
#pragma unroll
    for (int i = 0; i < 8; i++) {
        float* Cp = &g_gates[(bm + tm + i) * H3 + bn + tn];
        *(float4*)(Cp + 0) = make_float4(acc[i][0], acc[i][1], acc[i][2], acc[i][3]);
        *(float4*)(Cp + 4) = make_float4(acc[i][4], acc[i][5], acc[i][6], acc[i][7]);
    }
}

// ---------------------------------------------------------------------------
// GRU elementwise + i_n recompute + per-row reductions (logits, out, loss)
// One CTA handles ROWS_PER_CTA rows. Dynamic smem: W_ih n-gate rows + b_ih.
//   sw[j*14 + 0]      = b_ih[2048+j]
//   sw[j*14 + 1 + f]  = W_ih[(2048+j)*13 + f]   (f=0: dec col, f=1..12: aux)
// ---------------------------------------------------------------------------
__global__ void __launch_bounds__(256) k_gru(
    const float* __restrict__ W_ih, const float* __restrict__ b_ih,
    const float* __restrict__ emb, const float* __restrict__ W_out,
    const float* __restrict__ b_out, const int* __restrict__ st,
    float* __restrict__ outp, int t)
{
    extern __shared__ float sw[];  // 1024*14 floats = 57344 B
    __shared__ float red[8][6];
    int tid = threadIdx.x;

    for (int idx = tid; idx < HID * 14; idx += 256) {
        int j = idx / 14;
        int c = idx - j * 14;
        sw[idx] = (c == 0) ? b_ih[2048 + j] : W_ih[(2048 + j) * 13 + (c - 1)];
    }
    __syncthreads();

    float loss_local = 0.0f;
    float bout = b_out[0];

    for (int rr = 0; rr < ROWS_PER_CTA; rr++) {
        int row = blockIdx.x * ROWS_PER_CTA + rr;
        const float* Ar = &g_A[row * KP];
        float dec = Ar[1024];
        float ax[12];
#pragma unroll
        for (int f = 0; f < 12; f++) ax[f] = Ar[1025 + f];

        float e0 = 0.f, e1 = 0.f, e2 = 0.f, e3 = 0.f, e4 = 0.f, od = 0.f;
        const float* gr = &g_gates[row * H3];

        for (int j = tid; j < HID; j += 256) {
            float r = sigmoidf_(gr[j]);
            float z = sigmoidf_(gr[1024 + j]);
            const float* w = &sw[j * 14];
            float in_ = fmaf(dec, w[1], w[0]);
#pragma unroll
            for (int f = 0; f < 12; f++) in_ = fmaf(ax[f], w[2 + f], in_);
            float n = tanhf(fmaf(r, gr[2048 + j], in_));
            float hp = g_A[row * KP + j];
            float h = (1.0f - z) * n + z * hp;
            g_A[row * KP + j] = h;
            e0 = fmaf(h, emb[0 * HID + j], e0);
            e1 = fmaf(h, emb[1 * HID + j], e1);
            e2 = fmaf(h, emb[2 * HID + j], e2);
            e3 = fmaf(h, emb[3 * HID + j], e3);
            e4 = fmaf(h, emb[4 * HID + j], e4);
            od = fmaf(h, W_out[j], od);
        }

        float vals[6] = {e0, e1, e2, e3, e4, od};
#pragma unroll
        for (int s = 16; s > 0; s >>= 1)
#pragma unroll
            for (int vv = 0; vv < 6; vv++)
                vals[vv] += __shfl_down_sync(0xffffffffu, vals[vv], s);
        if ((tid & 31) == 0)
#pragma unroll
            for (int vv = 0; vv < 6; vv++) red[tid >> 5][vv] = vals[vv];
        __syncthreads();
        if (tid == 0) {
            float l[6];
#pragma unroll
            for (int vv = 0; vv < 6; vv++) {
                float s = 0.f;
#pragma unroll
                for (int w8 = 0; w8 < 8; w8++) s += red[w8][vv];
                l[vv] = s;
            }
            float mx = l[0];
#pragma unroll
            for (int k2 = 1; k2 < 5; k2++) mx = fmaxf(mx, l[k2]);
            float se = 0.f;
#pragma unroll
            for (int k2 = 0; k2 < 5; k2++) se += expf(l[k2] - mx);
            float lse = mx + logf(se);
            int pos = st[row * TT + t];
            loss_local += lse - l[pos];
            float o = l[5] + bout;
            g_cur[row] = o;
            outp[row * TT + t] = o;
        }
        __syncthreads();
    }
    if (tid == 0) atomicAdd(&g_loss, loss_local);
}

// ---------------------------------------------------------------------------
__global__ void k_final(float* outp, int out_size) {
    if (out_size > BSZ * TT)
        outp[BSZ * TT] = g_loss * (1.0f / ((float)BSZ * (float)TT));
}

// ---------------------------------------------------------------------------
extern "C" void kernel_launch(void* const* d_in, const int* in_sizes, int n_in,
                              void* d_out, int out_size) {
    const float* aux    = (const float*)d_in[0];
    const float* cur_pm = (const float*)d_in[1];
    const float* hn     = (const float*)d_in[2];
    const int*   st     = (const int*)  d_in[3];
    const float* tgt    = (const float*)d_in[4];
    const float* v      = (const float*)d_in[5];
    const float* W_ih   = (const float*)d_in[6];
    const float* W_hh   = (const float*)d_in[7];
    const float* b_ih   = (const float*)d_in[8];
    const float* b_hh   = (const float*)d_in[9];
    const float* emb    = (const float*)d_in[10];
    const float* W_out  = (const float*)d_in[11];
    const float* b_out  = (const float*)d_in[12];
    float* outp = (float*)d_out;

    cudaFuncSetAttribute(k_gru, cudaFuncAttributeMaxDynamicSharedMemorySize, 14 * HID * 4);

    k_init<<<BSZ, 256>>>(hn, cur_pm);
    k_wbig<<<2048, 256>>>(W_hh, W_ih, b_ih, b_hh);

    dim3 gg(H3 / 128, BSZ / 128);
    for (int t = 0; t < TT; t++) {
        k_xfill<<<(BSZ + 255) / 256, 256>>>(aux, tgt, v, t);
        k_gemm<<<gg, 256>>>();
        k_gru<<<BSZ / ROWS_PER_CTA, 256, 14 * HID * 4>>>(W_ih, b_ih, emb, W_out, b_out, st, outp, t);
    }
    k_final<<<1, 1>>>(outp, out_size);
}

// round 8
// speedup vs baseline: 1.9840x; 1.9823x over previous
#include <cuda_runtime.h>
#include <cuda_bf16.h>
#include <cstdint>
#include <math.h>

#define BSZ 4096
#define TT  24
#define HID 1024
#define H3  3072
#define SEC 1040          // one K-section: 1024 h + 1 dec + 12 aux + 1 bias + 2 pad
#define KB3 3136          // 3*SEC = 3120 padded to multiple of 64
#define CHUNKS 49         // KB3 / 64
#define STAGES 3
#define ROWS_PER_CTA 16

// ---------------- device globals (no cudaMalloc anywhere) ----------------
__device__ __nv_bfloat16 g_Abf[(size_t)BSZ * KB3];  // [A_hi | A_lo | A_hi] per row
__device__ __nv_bfloat16 g_Wbf[(size_t)H3 * KB3];   // [W_hi | W_hi | W_lo] per row
__device__ float g_gates[(size_t)BSZ * H3];         // GEMM out: [r | z | h_n]
__device__ float g_H[(size_t)BSZ * HID];            // fp32 hidden state
__device__ float g_cur[BSZ];
__device__ float g_loss;

__device__ __forceinline__ float sigmoidf_(float x) { return 1.0f / (1.0f + expf(-x)); }

__device__ __forceinline__ void split_bf(float x, __nv_bfloat16& hi, __nv_bfloat16& lo) {
    hi = __float2bfloat16(x);
    lo = __float2bfloat16(x - __bfloat162float(hi));
}

// ---------------- PTX helpers (compute_100-safe only) ----------------
__device__ __forceinline__ uint32_t smem_u32(const void* p) {
    uint32_t a;
    asm("{ .reg .u64 t; cvta.to.shared.u64 t, %1; cvt.u32.u64 %0, t; }" : "=r"(a) : "l"(p));
    return a;
}
__device__ __forceinline__ void cp_async16(uint32_t dst, const void* src) {
    asm volatile("cp.async.cg.shared.global [%0], [%1], 16;\n" :: "r"(dst), "l"(src));
}
__device__ __forceinline__ void cp_commit() { asm volatile("cp.async.commit_group;\n"); }
template <int N> __device__ __forceinline__ void cp_waitg() {
    asm volatile("cp.async.wait_group %0;\n" :: "n"(N));
}
__device__ __forceinline__ void ldm_x4(uint32_t& r0, uint32_t& r1, uint32_t& r2, uint32_t& r3,
                                       uint32_t addr) {
    asm volatile("ldmatrix.sync.aligned.m8n8.x4.shared.b16 {%0,%1,%2,%3}, [%4];"
                 : "=r"(r0), "=r"(r1), "=r"(r2), "=r"(r3) : "r"(addr));
}
__device__ __forceinline__ void mma_bf16(float& c0, float& c1, float& c2, float& c3,
                                         uint32_t a0, uint32_t a1, uint32_t a2, uint32_t a3,
                                         uint32_t b0, uint32_t b1) {
    asm volatile("mma.sync.aligned.m16n8k16.row.col.f32.bf16.bf16.f32 "
                 "{%0,%1,%2,%3}, {%4,%5,%6,%7}, {%8,%9}, {%0,%1,%2,%3};"
                 : "+f"(c0), "+f"(c1), "+f"(c2), "+f"(c3)
                 : "r"(a0), "r"(a1), "r"(a2), "r"(a3), "r"(b0), "r"(b1));
}
__device__ __forceinline__ uint32_t sw128(uint32_t bo) { return bo ^ ((bo >> 3) & 0x70); }

// ---------------------------------------------------------------------------
// Init: A" <- split(hn), g_H <- hn, pads <- 0, cur <- current_pm25, loss <- 0
// ---------------------------------------------------------------------------
__global__ void k_init(const float* __restrict__ hn, const float* __restrict__ cur_pm) {
    int row = blockIdx.x;
    __nv_bfloat16* Ab = g_Abf + (size_t)row * KB3;
    for (int j = threadIdx.x; j < HID; j += blockDim.x) {
        float x = hn[row * HID + j];
        __nv_bfloat16 hi, lo;
        split_bf(x, hi, lo);
        Ab[j] = hi; Ab[SEC + j] = lo; Ab[2 * SEC + j] = hi;
        g_H[row * HID + j] = x;
    }
    if (threadIdx.x < 16) Ab[3120 + threadIdx.x] = __float2bfloat16(0.0f);
    if (threadIdx.x == 0) {
        __nv_bfloat16 z = __float2bfloat16(0.0f);
        for (int s = 0; s < 3; s++) { Ab[s * SEC + 1038] = z; Ab[s * SEC + 1039] = z; }
        g_cur[row] = cur_pm[row];
        if (row == 0) g_loss = 0.0f;
    }
}

// ---------------------------------------------------------------------------
// Build W" bf16 [3072 x 3136]: sections [W_hi | W_hi | W_lo]
// ---------------------------------------------------------------------------
__global__ void k_wbf(const float* __restrict__ W_hh, const float* __restrict__ W_ih,
                      const float* __restrict__ b_ih, const float* __restrict__ b_hh) {
    size_t total = (size_t)H3 * KB3;
    for (size_t idx = (size_t)blockIdx.x * blockDim.x + threadIdx.x; idx < total;
         idx += (size_t)gridDim.x * blockDim.x) {
        int c = (int)(idx / KB3);
        int k = (int)(idx - (size_t)c * KB3);
        __nv_bfloat16 outv;
        if (k >= 3120) {
            outv = __float2bfloat16(0.0f);
        } else {
            int sec = k / SEC;
            int kk = k - sec * SEC;
            float val;
            if (kk < 1024) val = W_hh[c * 1024 + kk];
            else if (kk <= 1036) val = (c < 2048) ? W_ih[c * 13 + (kk - 1024)] : 0.0f;
            else if (kk == 1037) val = (c < 2048) ? (b_ih[c] + b_hh[c]) : b_hh[c];
            else val = 0.0f;
            __nv_bfloat16 hi, lo;
            split_bf(val, hi, lo);
            outv = (sec < 2) ? hi : lo;
        }
        g_Wbf[idx] = outv;
    }
}

// ---------------------------------------------------------------------------
// Per-step x-fill
// ---------------------------------------------------------------------------
__global__ void k_xfill(const float* __restrict__ aux, const float* __restrict__ tgt_seq,
                        const float* __restrict__ v, int t) {
    int row = blockIdx.x * blockDim.x + threadIdx.x;
    if (row >= BSZ) return;
    float dec;
    if (t == 0) {
        dec = g_cur[row];
    } else {
        float tg = tgt_seq[row * TT + (t - 1)];
        float m = (tg != 0.0f) ? v[row * TT + t] : 0.0f;
        dec = (m == 1.0f) ? tg : g_cur[row];
    }
    __nv_bfloat16* Ab = g_Abf + (size_t)row * KB3;
    float xv[14];
    xv[0] = dec;
#pragma unroll
    for (int f = 0; f < 12; f++) xv[1 + f] = aux[(row * TT + t) * 12 + f];
    xv[13] = 1.0f;
#pragma unroll
    for (int i = 0; i < 14; i++) {
        __nv_bfloat16 hi, lo;
        split_bf(xv[i], hi, lo);
        Ab[1024 + i] = hi;
        Ab[SEC + 1024 + i] = lo;
        Ab[2 * SEC + 1024 + i] = hi;
    }
}

// ---------------------------------------------------------------------------
// Tensor-core GEMM via mma.sync (HMMA path, compute_100-safe):
//   gates[m][n] = sum_k A"[m][k] * W"[n][k]
// 128x128 CTA tile, K-chunks of 64 bf16 (128B rows, SW128 swizzle),
// 3-stage cp.async pipeline, 8 warps in 2(m)x4(n), each 64x32 via m16n8k16.
// ---------------------------------------------------------------------------
__global__ void __launch_bounds__(256) k_gemm_mma() {
    extern __shared__ char smem[];
    uint32_t sb = smem_u32(smem);
    const int tid = threadIdx.x;
    const int wid = tid >> 5;
    const int lane = tid & 31;
    const int bn = blockIdx.x * 128;  // 24 N-tiles
    const int bm = blockIdx.y * 128;  // 32 M-tiles
    const int wm = wid >> 2;          // 0..1 -> 64-row slab
    const int wn = wid & 3;           // 0..3 -> 32-col slab

    const __nv_bfloat16* Ag = g_Abf + (size_t)bm * KB3;
    const __nv_bfloat16* Wg = g_Wbf + (size_t)bn * KB3;

    float acc[4][4][4];
#pragma unroll
    for (int i = 0; i < 4; i++)
#pragma unroll
        for (int j = 0; j < 4; j++)
#pragma unroll
            for (int v2 = 0; v2 < 4; v2++) acc[i][j][v2] = 0.0f;

    // ldmatrix per-lane row/col constants
    const int rA = (lane & 7) + ((lane >> 3) & 1) * 8;  // row within 16-row tile
    const int cA = (lane >> 4) * 16;                    // byte col half (k0-7 / k8-15)
    const int rB = lane & 7;                            // n-row within 8
    const int hB = ((lane >> 3) & 1) * 16;              // k half bytes
    const int pB = (lane >> 4);                         // n-tile parity within pair

#define FILL(s, c) do {                                                          \
    uint32_t _ab = sb + (uint32_t)(s) * 32768u;                                  \
    uint32_t _bb = _ab + 16384u;                                                 \
    _Pragma("unroll")                                                            \
    for (int q = 0; q < 4; q++) {                                                \
        int i = tid + q * 256;                                                   \
        int row = i >> 3, seg = i & 7;                                           \
        uint32_t bo = (uint32_t)(row * 128 + seg * 16);                          \
        uint32_t sw = sw128(bo);                                                 \
        const char* ga = (const char*)(Ag + (size_t)row * KB3 + (c) * 64) + seg * 16; \
        const char* gb = (const char*)(Wg + (size_t)row * KB3 + (c) * 64) + seg * 16; \
        cp_async16(_ab + sw, ga);                                                \
        cp_async16(_bb + sw, gb);                                                \
    }                                                                            \
} while (0)

    FILL(0, 0); cp_commit();
    FILL(1, 1); cp_commit();

    for (int c = 0; c < CHUNKS; c++) {
        int s = c % STAGES;
        int cn = c + 2;
        if (cn < CHUNKS) {
            FILL(cn % STAGES, cn);
            cp_commit();
            cp_waitg<2>();
        } else if (c == CHUNKS - 2) {
            cp_waitg<1>();
        } else {
            cp_waitg<0>();
        }
        __syncthreads();

        uint32_t ab = sb + (uint32_t)s * 32768u;
        uint32_t bb = ab + 16384u;
#pragma unroll
        for (int kk = 0; kk < 4; kk++) {
            uint32_t a[4][4];
#pragma unroll
            for (int mt = 0; mt < 4; mt++) {
                uint32_t bo = (uint32_t)((wm * 64 + mt * 16 + rA) * 128 + kk * 32 + cA);
                ldm_x4(a[mt][0], a[mt][1], a[mt][2], a[mt][3], ab + sw128(bo));
            }
            uint32_t b[4][2];
#pragma unroll
            for (int ntp = 0; ntp < 2; ntp++) {
                uint32_t bo = (uint32_t)((wn * 32 + (ntp * 2 + pB) * 8 + rB) * 128 + kk * 32 + hB);
                ldm_x4(b[ntp * 2][0], b[ntp * 2][1], b[ntp * 2 + 1][0], b[ntp * 2 + 1][1],
                       bb + sw128(bo));
            }
#pragma unroll
            for (int mt = 0; mt < 4; mt++)
#pragma unroll
                for (int nt = 0; nt < 4; nt++)
                    mma_bf16(acc[mt][nt][0], acc[mt][nt][1], acc[mt][nt][2], acc[mt][nt][3],
                             a[mt][0], a[mt][1], a[mt][2], a[mt][3],
                             b[nt][0], b[nt][1]);
        }
        __syncthreads();
    }
#undef FILL

    // epilogue: c0,c1 -> (row = quad, cols 2*tig+{0,1}); c2,c3 -> row+8
    int quad = lane >> 2;
    int tig = lane & 3;
#pragma unroll
    for (int mt = 0; mt < 4; mt++) {
        int row0 = bm + wm * 64 + mt * 16 + quad;
#pragma unroll
        for (int nt = 0; nt < 4; nt++) {
            int col = bn + wn * 32 + nt * 8 + tig * 2;
            *(float2*)&g_gates[(size_t)row0 * H3 + col] =
                make_float2(acc[mt][nt][0], acc[mt][nt][1]);
            *(float2*)&g_gates[(size_t)(row0 + 8) * H3 + col] =
                make_float2(acc[mt][nt][2], acc[mt][nt][3]);
        }
    }
}

// ---------------------------------------------------------------------------
// GRU elementwise + i_n recompute + per-row reductions (logits, out, loss)
// ---------------------------------------------------------------------------
__global__ void __launch_bounds__(256) k_gru(
    const float* __restrict__ W_ih, const float* __restrict__ b_ih,
    const float* __restrict__ emb, const float* __restrict__ W_out,
    const float* __restrict__ b_out, const int* __restrict__ st,
    float* __restrict__ outp, int t)
{
    extern __shared__ float sw[];  // HID*14 floats
    __shared__ float red[8][6];
    int tid = threadIdx.x;

    for (int idx = tid; idx < HID * 14; idx += 256) {
        int j = idx / 14;
        int c = idx - j * 14;
        sw[idx] = (c == 0) ? b_ih[2048 + j] : W_ih[(2048 + j) * 13 + (c - 1)];
    }
    __syncthreads();

    float loss_local = 0.0f;
    float bout = b_out[0];

    for (int rr = 0; rr < ROWS_PER_CTA; rr++) {
        int row = blockIdx.x * ROWS_PER_CTA + rr;
        __nv_bfloat16* Ab = g_Abf + (size_t)row * KB3;
        float dec = __bfloat162float(Ab[1024]) + __bfloat162float(Ab[SEC + 1024]);
        float ax[12];
#pragma unroll
        for (int f = 0; f < 12; f++)
            ax[f] = __bfloat162float(Ab[1025 + f]) + __bfloat162float(Ab[SEC + 1025 + f]);

        float e0 = 0.f, e1 = 0.f, e2 = 0.f, e3 = 0.f, e4 = 0.f, od = 0.f;
        const float* gr = &g_gates[(size_t)row * H3];

        for (int j = tid; j < HID; j += 256) {
            float r = sigmoidf_(gr[j]);
            float z = sigmoidf_(gr[1024 + j]);
            const float* w = &sw[j * 14];
            float in_ = fmaf(dec, w[1], w[0]);
#pragma unroll
            for (int f = 0; f < 12; f++) in_ = fmaf(ax[f], w[2 + f], in_);
            float n = tanhf(fmaf(r, gr[2048 + j], in_));
            float hp = g_H[(size_t)row * HID + j];
            float h = (1.0f - z) * n + z * hp;
            g_H[(size_t)row * HID + j] = h;
            __nv_bfloat16 hi, lo;
            split_bf(h, hi, lo);
            Ab[j] = hi; Ab[SEC + j] = lo; Ab[2 * SEC + j] = hi;
            e0 = fmaf(h, emb[0 * HID + j], e0);
            e1 = fmaf(h, emb[1 * HID + j], e1);
            e2 = fmaf(h, emb[2 * HID + j], e2);
            e3 = fmaf(h, emb[3 * HID + j], e3);
            e4 = fmaf(h, emb[4 * HID + j], e4);
            od = fmaf(h, W_out[j], od);
        }

        float vals[6] = {e0, e1, e2, e3, e4, od};
#pragma unroll
        for (int s = 16; s > 0; s >>= 1)
#pragma unroll
            for (int vv = 0; vv < 6; vv++)
                vals[vv] += __shfl_down_sync(0xffffffffu, vals[vv], s);
        if ((tid & 31) == 0)
#pragma unroll
            for (int vv = 0; vv < 6; vv++) red[tid >> 5][vv] = vals[vv];
        __syncthreads();
        if (tid == 0) {
            float l[6];
#pragma unroll
            for (int vv = 0; vv < 6; vv++) {
                float s = 0.f;
#pragma unroll
                for (int w8 = 0; w8 < 8; w8++) s += red[w8][vv];
                l[vv] = s;
            }
            float mx = l[0];
#pragma unroll
            for (int k2 = 1; k2 < 5; k2++) mx = fmaxf(mx, l[k2]);
            float se = 0.f;
#pragma unroll
            for (int k2 = 0; k2 < 5; k2++) se += expf(l[k2] - mx);
            float lse = mx + logf(se);
            int pos = st[row * TT + t];
            loss_local += lse - l[pos];
            float o = l[5] + bout;
            g_cur[row] = o;
            outp[row * TT + t] = o;
        }
        __syncthreads();
    }
    if (tid == 0) atomicAdd(&g_loss, loss_local);
}

// ---------------------------------------------------------------------------
__global__ void k_final(float* outp, int out_size) {
    if (out_size > BSZ * TT)
        outp[BSZ * TT] = g_loss * (1.0f / ((float)BSZ * (float)TT));
}

// ---------------------------------------------------------------------------
extern "C" void kernel_launch(void* const* d_in, const int* in_sizes, int n_in,
                              void* d_out, int out_size) {
    const float* aux    = (const float*)d_in[0];
    const float* cur_pm = (const float*)d_in[1];
    const float* hn     = (const float*)d_in[2];
    const int*   st     = (const int*)  d_in[3];
    const float* tgt    = (const float*)d_in[4];
    const float* v      = (const float*)d_in[5];
    const float* W_ih   = (const float*)d_in[6];
    const float* W_hh   = (const float*)d_in[7];
    const float* b_ih   = (const float*)d_in[8];
    const float* b_hh   = (const float*)d_in[9];
    const float* emb    = (const float*)d_in[10];
    const float* W_out  = (const float*)d_in[11];
    const float* b_out  = (const float*)d_in[12];
    float* outp = (float*)d_out;

    const int gemm_smem = STAGES * 32768;
    cudaFuncSetAttribute(k_gru, cudaFuncAttributeMaxDynamicSharedMemorySize, 14 * HID * 4);
    cudaFuncSetAttribute(k_gemm_mma, cudaFuncAttributeMaxDynamicSharedMemorySize, gemm_smem);

    k_init<<<BSZ, 256>>>(hn, cur_pm);
    k_wbf<<<2048, 256>>>(W_hh, W_ih, b_ih, b_hh);

    dim3 gg(H3 / 128, BSZ / 128);
    for (int t = 0; t < TT; t++) {
        k_xfill<<<(BSZ + 255) / 256, 256>>>(aux, tgt, v, t);
        k_gemm_mma<<<gg, 256, gemm_smem>>>();
        k_gru<<<BSZ / ROWS_PER_CTA, 256, 14 * HID * 4>>>(W_ih, b_ih, emb, W_out, b_out, st, outp, t);
    }
    k_final<<<1, 1>>>(outp, out_size);
}

// round 9
// speedup vs baseline: 2.3960x; 1.2077x over previous
#include <cuda_runtime.h>
#include <cuda_bf16.h>
#include <cstdint>
#include <math.h>

#define BSZ 4096
#define TT  24
#define HID 1024
#define H3  3072
#define SEC 1040          // one K-section: 1024 h + 1 dec + 12 aux + 1 bias + 2 pad
#define KB3 3136          // 3*SEC = 3120 padded to multiple of 64
#define CHUNKS 49         // KB3 / 64
#define STAGES 4
#define GRU_WARPS 8

// ---------------- device globals (no cudaMalloc anywhere) ----------------
__device__ __nv_bfloat16 g_Abf[(size_t)BSZ * KB3];  // [A_hi | A_lo | A_hi] per row
__device__ __nv_bfloat16 g_Wbf[(size_t)H3 * KB3];   // [W_hi | W_hi | W_lo] per row
__device__ float g_gates[(size_t)BSZ * H3];         // GEMM out: [r | z | h_n]
__device__ float g_H[(size_t)BSZ * HID];            // fp32 hidden state
__device__ float g_loss;

__device__ __forceinline__ float tanh_fast(float x) {
    float y;
    asm("tanh.approx.f32 %0, %1;" : "=f"(y) : "f"(x));
    return y;
}
__device__ __forceinline__ float sigmoid_fast(float x) {
    return 0.5f * tanh_fast(0.5f * x) + 0.5f;
}

__device__ __forceinline__ void split_bf(float x, __nv_bfloat16& hi, __nv_bfloat16& lo) {
    hi = __float2bfloat16(x);
    lo = __float2bfloat16(x - __bfloat162float(hi));
}

// ---------------- PTX helpers (compute_100-safe only) ----------------
__device__ __forceinline__ uint32_t smem_u32(const void* p) {
    uint32_t a;
    asm("{ .reg .u64 t; cvta.to.shared.u64 t, %1; cvt.u32.u64 %0, t; }" : "=r"(a) : "l"(p));
    return a;
}
__device__ __forceinline__ void cp_async16(uint32_t dst, const void* src) {
    asm volatile("cp.async.cg.shared.global [%0], [%1], 16;\n" :: "r"(dst), "l"(src));
}
__device__ __forceinline__ void cp_commit() { asm volatile("cp.async.commit_group;\n"); }
template <int N> __device__ __forceinline__ void cp_waitg() {
    asm volatile("cp.async.wait_group %0;\n" :: "n"(N));
}
__device__ __forceinline__ void ldm_x4(uint32_t& r0, uint32_t& r1, uint32_t& r2, uint32_t& r3,
                                       uint32_t addr) {
    asm volatile("ldmatrix.sync.aligned.m8n8.x4.shared.b16 {%0,%1,%2,%3}, [%4];"
                 : "=r"(r0), "=r"(r1), "=r"(r2), "=r"(r3) : "r"(addr));
}
__device__ __forceinline__ void mma_bf16(float& c0, float& c1, float& c2, float& c3,
                                         uint32_t a0, uint32_t a1, uint32_t a2, uint32_t a3,
                                         uint32_t b0, uint32_t b1) {
    asm volatile("mma.sync.aligned.m16n8k16.row.col.f32.bf16.bf16.f32 "
                 "{%0,%1,%2,%3}, {%4,%5,%6,%7}, {%8,%9}, {%0,%1,%2,%3};"
                 : "+f"(c0), "+f"(c1), "+f"(c2), "+f"(c3)
                 : "r"(a0), "r"(a1), "r"(a2), "r"(a3), "r"(b0), "r"(b1));
}
__device__ __forceinline__ uint32_t sw128(uint32_t bo) { return bo ^ ((bo >> 3) & 0x70); }

// ---------------------------------------------------------------------------
// Init: A" <- split(hn), g_H <- hn, pads <- 0, t=0 x-columns, loss <- 0
// ---------------------------------------------------------------------------
__global__ void k_init(const float* __restrict__ hn, const float* __restrict__ cur_pm,
                       const float* __restrict__ aux) {
    int row = blockIdx.x;
    int tid = threadIdx.x;
    __nv_bfloat16* Ab = g_Abf + (size_t)row * KB3;
    for (int j = tid; j < HID; j += blockDim.x) {
        float x = hn[row * HID + j];
        __nv_bfloat16 hi, lo;
        split_bf(x, hi, lo);
        Ab[j] = hi; Ab[SEC + j] = lo; Ab[2 * SEC + j] = hi;
        g_H[row * HID + j] = x;
    }
    if (tid < 16) Ab[3120 + tid] = __float2bfloat16(0.0f);
    // t=0 x-fill: dec = current_pm25 (i==0 branch of the reference)
    if (tid < 14) {
        float xv = (tid == 0) ? cur_pm[row]
                 : (tid == 13) ? 1.0f
                 : aux[(row * TT + 0) * 12 + (tid - 1)];
        __nv_bfloat16 hi, lo;
        split_bf(xv, hi, lo);
        Ab[1024 + tid] = hi;
        Ab[SEC + 1024 + tid] = lo;
        Ab[2 * SEC + 1024 + tid] = hi;
    }
    if (tid == 0) {
        __nv_bfloat16 z = __float2bfloat16(0.0f);
        for (int s = 0; s < 3; s++) { Ab[s * SEC + 1038] = z; Ab[s * SEC + 1039] = z; }
        if (row == 0) g_loss = 0.0f;
    }
}

// ---------------------------------------------------------------------------
// Build W" bf16 [3072 x 3136]: sections [W_hi | W_hi | W_lo]
// ---------------------------------------------------------------------------
__global__ void k_wbf(const float* __restrict__ W_hh, const float* __restrict__ W_ih,
                      const float* __restrict__ b_ih, const float* __restrict__ b_hh) {
    size_t total = (size_t)H3 * KB3;
    for (size_t idx = (size_t)blockIdx.x * blockDim.x + threadIdx.x; idx < total;
         idx += (size_t)gridDim.x * blockDim.x) {
        int c = (int)(idx / KB3);
        int k = (int)(idx - (size_t)c * KB3);
        __nv_bfloat16 outv;
        if (k >= 3120) {
            outv = __float2bfloat16(0.0f);
        } else {
            int sec = k / SEC;
            int kk = k - sec * SEC;
            float val;
            if (kk < 1024) val = W_hh[c * 1024 + kk];
            else if (kk <= 1036) val = (c < 2048) ? W_ih[c * 13 + (kk - 1024)] : 0.0f;
            else if (kk == 1037) val = (c < 2048) ? (b_ih[c] + b_hh[c]) : b_hh[c];
            else val = 0.0f;
            __nv_bfloat16 hi, lo;
            split_bf(val, hi, lo);
            outv = (sec < 2) ? hi : lo;
        }
        g_Wbf[idx] = outv;
    }
}

// ---------------------------------------------------------------------------
// Tensor-core GEMM via mma.sync: gates[m][n] = sum_k A"[m][k] * W"[n][k]
// 128x128 CTA tile, K-chunks of 64 bf16 (SW128), 4-stage cp.async pipeline,
// ONE __syncthreads per chunk. 8 warps 2(m)x4(n), each 64x32 via m16n8k16.
// ---------------------------------------------------------------------------
__global__ void __launch_bounds__(256) k_gemm_mma() {
    extern __shared__ char smem[];
    uint32_t sb = smem_u32(smem);
    const int tid = threadIdx.x;
    const int wid = tid >> 5;
    const int lane = tid & 31;
    const int bn = blockIdx.x * 128;  // 24 N-tiles
    const int bm = blockIdx.y * 128;  // 32 M-tiles
    const int wm = wid >> 2;          // 0..1 -> 64-row slab
    const int wn = wid & 3;           // 0..3 -> 32-col slab

    const __nv_bfloat16* Ag = g_Abf + (size_t)bm * KB3;
    const __nv_bfloat16* Wg = g_Wbf + (size_t)bn * KB3;

    float acc[4][4][4];
#pragma unroll
    for (int i = 0; i < 4; i++)
#pragma unroll
        for (int j = 0; j < 4; j++)
#pragma unroll
            for (int v2 = 0; v2 < 4; v2++) acc[i][j][v2] = 0.0f;

    const int rA = (lane & 7) + ((lane >> 3) & 1) * 8;
    const int cA = (lane >> 4) * 16;
    const int rB = lane & 7;
    const int hB = ((lane >> 3) & 1) * 16;
    const int pB = (lane >> 4);

#define FILL(s, c) do {                                                          \
    uint32_t _ab = sb + (uint32_t)(s) * 32768u;                                  \
    uint32_t _bb = _ab + 16384u;                                                 \
    _Pragma("unroll")                                                            \
    for (int q = 0; q < 4; q++) {                                                \
        int i = tid + q * 256;                                                   \
        int row = i >> 3, seg = i & 7;                                           \
        uint32_t bo = (uint32_t)(row * 128 + seg * 16);                          \
        uint32_t sw = sw128(bo);                                                 \
        const char* ga = (const char*)(Ag + (size_t)row * KB3 + (c) * 64) + seg * 16; \
        const char* gb = (const char*)(Wg + (size_t)row * KB3 + (c) * 64) + seg * 16; \
        cp_async16(_ab + sw, ga);                                                \
        cp_async16(_bb + sw, gb);                                                \
    }                                                                            \
} while (0)

    FILL(0, 0); cp_commit();
    FILL(1, 1); cp_commit();
    FILL(2, 2); cp_commit();

    for (int c = 0; c < CHUNKS; c++) {
        // waitg publishes chunk c (groups complete in order); the single barrier
        // both makes chunk c visible to all warps AND certifies stage (c+3)&3
        // (last read during iter c-1) is reusable.
        if (c + 3 < CHUNKS) {
            cp_waitg<2>();
            __syncthreads();
            FILL((c + 3) & 3, c + 3);
            cp_commit();
        } else if (c + 3 == CHUNKS) {
            cp_waitg<2>();
            __syncthreads();
        } else if (c + 2 == CHUNKS) {
            cp_waitg<1>();
            __syncthreads();
        } else {
            cp_waitg<0>();
            __syncthreads();
        }

        uint32_t ab = sb + (uint32_t)(c & 3) * 32768u;
        uint32_t bb = ab + 16384u;
#pragma unroll
        for (int kk = 0; kk < 4; kk++) {
            uint32_t a[4][4];
#pragma unroll
            for (int mt = 0; mt < 4; mt++) {
                uint32_t bo = (uint32_t)((wm * 64 + mt * 16 + rA) * 128 + kk * 32 + cA);
                ldm_x4(a[mt][0], a[mt][1], a[mt][2], a[mt][3], ab + sw128(bo));
            }
            uint32_t b[4][2];
#pragma unroll
            for (int ntp = 0; ntp < 2; ntp++) {
                uint32_t bo = (uint32_t)((wn * 32 + (ntp * 2 + pB) * 8 + rB) * 128 + kk * 32 + hB);
                ldm_x4(b[ntp * 2][0], b[ntp * 2][1], b[ntp * 2 + 1][0], b[ntp * 2 + 1][1],
                       bb + sw128(bo));
            }
#pragma unroll
            for (int mt = 0; mt < 4; mt++)
#pragma unroll
                for (int nt = 0; nt < 4; nt++)
                    mma_bf16(acc[mt][nt][0], acc[mt][nt][1], acc[mt][nt][2], acc[mt][nt][3],
                             a[mt][0], a[mt][1], a[mt][2], a[mt][3],
                             b[nt][0], b[nt][1]);
        }
    }
#undef FILL

    int quad = lane >> 2;
    int tig = lane & 3;
#pragma unroll
    for (int mt = 0; mt < 4; mt++) {
        int row0 = bm + wm * 64 + mt * 16 + quad;
#pragma unroll
        for (int nt = 0; nt < 4; nt++) {
            int col = bn + wn * 32 + nt * 8 + tig * 2;
            *(float2*)&g_gates[(size_t)row0 * H3 + col] =
                make_float2(acc[mt][nt][0], acc[mt][nt][1]);
            *(float2*)&g_gates[(size_t)(row0 + 8) * H3 + col] =
                make_float2(acc[mt][nt][2], acc[mt][nt][3]);
        }
    }
}

// ---------------------------------------------------------------------------
// Warp-per-row GRU elementwise + reductions + fused x-fill for step t+1.
// 512 CTAs x 8 warps. No block barriers in the row path.
// smem: swn[1024*14] (n-gate W_ih rows + b_ih), ew[1024*6] (emb x5 + W_out)
// ---------------------------------------------------------------------------
__global__ void __launch_bounds__(256) k_gru_w(
    const float* __restrict__ W_ih, const float* __restrict__ b_ih,
    const float* __restrict__ emb, const float* __restrict__ W_out,
    const float* __restrict__ b_out, const int* __restrict__ st,
    const float* __restrict__ aux, const float* __restrict__ tgt_seq,
    const float* __restrict__ v, float* __restrict__ outp, int t)
{
    extern __shared__ float sh[];
    float* swn = sh;            // j*14: [b_ih_n | W_ih_n row (13)]
    float* ew  = sh + HID * 14; // j*6:  [emb0..emb4 | W_out]
    __shared__ float sloss;
    int tid = threadIdx.x;

    for (int idx = tid; idx < HID * 14; idx += 256) {
        int j = idx / 14, c = idx - j * 14;
        swn[idx] = (c == 0) ? b_ih[2048 + j] : W_ih[(2048 + j) * 13 + (c - 1)];
    }
    for (int idx = tid; idx < HID * 6; idx += 256) {
        int j = idx / 6, c = idx - j * 6;
        ew[idx] = (c < 5) ? emb[c * HID + j] : W_out[j];
    }
    if (tid == 0) sloss = 0.0f;
    __syncthreads();

    int lane = tid & 31;
    int wid = tid >> 5;
    int row = blockIdx.x * GRU_WARPS + wid;

    const float* gr = g_gates + (size_t)row * H3;
    __nv_bfloat16* Ab = g_Abf + (size_t)row * KB3;
    float* Hrow = g_H + (size_t)row * HID;

    float dec = __bfloat162float(Ab[1024]) + __bfloat162float(Ab[SEC + 1024]);
    float ax[12];
#pragma unroll
    for (int f = 0; f < 12; f++)
        ax[f] = __bfloat162float(Ab[1025 + f]) + __bfloat162float(Ab[SEC + 1025 + f]);

    float e0 = 0.f, e1 = 0.f, e2 = 0.f, e3 = 0.f, e4 = 0.f, od = 0.f;

#pragma unroll 4
    for (int j = lane; j < HID; j += 32) {
        float r = sigmoid_fast(gr[j]);
        float z = sigmoid_fast(gr[1024 + j]);
        const float* w = &swn[j * 14];
        float in_ = fmaf(dec, w[1], w[0]);
#pragma unroll
        for (int f = 0; f < 12; f++) in_ = fmaf(ax[f], w[2 + f], in_);
        float n = tanh_fast(fmaf(r, gr[2048 + j], in_));
        float hp = Hrow[j];
        float h = (1.0f - z) * n + z * hp;
        Hrow[j] = h;
        __nv_bfloat16 hi, lo;
        split_bf(h, hi, lo);
        Ab[j] = hi; Ab[SEC + j] = lo; Ab[2 * SEC + j] = hi;
        const float* e = &ew[j * 6];
        e0 = fmaf(h, e[0], e0);
        e1 = fmaf(h, e[1], e1);
        e2 = fmaf(h, e[2], e2);
        e3 = fmaf(h, e[3], e3);
        e4 = fmaf(h, e[4], e4);
        od = fmaf(h, e[5], od);
    }

    float vals[6] = {e0, e1, e2, e3, e4, od};
#pragma unroll
    for (int s = 16; s > 0; s >>= 1)
#pragma unroll
        for (int vv = 0; vv < 6; vv++)
            vals[vv] += __shfl_down_sync(0xffffffffu, vals[vv], s);

    float o = 0.0f;
    if (lane == 0) {
        float mx = vals[0];
#pragma unroll
        for (int k2 = 1; k2 < 5; k2++) mx = fmaxf(mx, vals[k2]);
        float se = 0.f;
#pragma unroll
        for (int k2 = 0; k2 < 5; k2++) se += __expf(vals[k2] - mx);
        float lse = mx + __logf(se);
        int pos = st[row * TT + t];
        atomicAdd(&sloss, lse - vals[pos]);
        o = vals[5] + b_out[0];
        outp[row * TT + t] = o;
    }
    o = __shfl_sync(0xffffffffu, o, 0);

    // fused x-fill for step t+1
    if (t + 1 < TT && lane < 14) {
        float xv;
        if (lane == 0) {
            float tg = tgt_seq[row * TT + t];
            float m = (tg != 0.0f) ? v[row * TT + t + 1] : 0.0f;
            xv = (m == 1.0f) ? tg : o;
        } else if (lane == 13) {
            xv = 1.0f;
        } else {
            xv = aux[(row * TT + t + 1) * 12 + (lane - 1)];
        }
        __nv_bfloat16 hi, lo;
        split_bf(xv, hi, lo);
        Ab[1024 + lane] = hi;
        Ab[SEC + 1024 + lane] = lo;
        Ab[2 * SEC + 1024 + lane] = hi;
    }

    __syncthreads();
    if (tid == 0) atomicAdd(&g_loss, sloss);
}

// ---------------------------------------------------------------------------
__global__ void k_final(float* outp, int out_size) {
    if (out_size > BSZ * TT)
        outp[BSZ * TT] = g_loss * (1.0f / ((float)BSZ * (float)TT));
}

// ---------------------------------------------------------------------------
extern "C" void kernel_launch(void* const* d_in, const int* in_sizes, int n_in,
                              void* d_out, int out_size) {
    const float* aux    = (const float*)d_in[0];
    const float* cur_pm = (const float*)d_in[1];
    const float* hn     = (const float*)d_in[2];
    const int*   st     = (const int*)  d_in[3];
    const float* tgt    = (const float*)d_in[4];
    const float* v      = (const float*)d_in[5];
    const float* W_ih   = (const float*)d_in[6];
    const float* W_hh   = (const float*)d_in[7];
    const float* b_ih   = (const float*)d_in[8];
    const float* b_hh   = (const float*)d_in[9];
    const float* emb    = (const float*)d_in[10];
    const float* W_out  = (const float*)d_in[11];
    const float* b_out  = (const float*)d_in[12];
    float* outp = (float*)d_out;

    const int gemm_smem = STAGES * 32768;          // 128 KB
    const int gru_smem  = (HID * 14 + HID * 6) * 4; // 80 KB
    cudaFuncSetAttribute(k_gru_w, cudaFuncAttributeMaxDynamicSharedMemorySize, gru_smem);
    cudaFuncSetAttribute(k_gemm_mma, cudaFuncAttributeMaxDynamicSharedMemorySize, gemm_smem);

    k_init<<<BSZ, 256>>>(hn, cur_pm, aux);
    k_wbf<<<2048, 256>>>(W_hh, W_ih, b_ih, b_hh);

    dim3 gg(H3 / 128, BSZ / 128);
    for (int t = 0; t < TT; t++) {
        k_gemm_mma<<<gg, 256, gemm_smem>>>();
        k_gru_w<<<BSZ / GRU_WARPS, 256, gru_smem>>>(W_ih, b_ih, emb, W_out, b_out, st,
                                                    aux, tgt, v, outp, t);
    }
    k_final<<<1, 1>>>(outp, out_size);
}

// round 10
// speedup vs baseline: 2.9620x; 1.2362x over previous
#include <cuda_runtime.h>
#include <cuda_bf16.h>
#include <cstdint>
#include <math.h>

#define BSZ 4096
#define TT  24
#define HID 1024
#define H3  3072
#define SEC 1040          // one K-section: 1024 h + 1 dec + 12 aux + 1 bias + 2 pad
#define KB3 3136          // 3*SEC = 3120 padded to multiple of 64
#define CHUNKS 49         // KB3 / 64
#define STAGES 3
#define GRU_WARPS 8

// ---------------- device globals (no cudaMalloc anywhere) ----------------
__device__ __nv_bfloat16 g_Abf[(size_t)BSZ * KB3];  // [A_hi | A_lo | A_hi] per row
__device__ __nv_bfloat16 g_Wbf[(size_t)H3 * KB3];   // [W_hi | W_hi | W_lo] per row
__device__ float g_gates[(size_t)BSZ * H3];         // GEMM out: [r | z | h_n]
__device__ float g_H[(size_t)BSZ * HID];            // fp32 hidden state
__device__ float g_inaux[(size_t)TT * BSZ * HID];   // aux-part of i_n, all steps
__device__ float g_loss;

__device__ __forceinline__ float tanh_fast(float x) {
    float y;
    asm("tanh.approx.f32 %0, %1;" : "=f"(y) : "f"(x));
    return y;
}
__device__ __forceinline__ float sigmoid_fast(float x) {
    return 0.5f * tanh_fast(0.5f * x) + 0.5f;
}

__device__ __forceinline__ void split_bf(float x, __nv_bfloat16& hi, __nv_bfloat16& lo) {
    hi = __float2bfloat16(x);
    lo = __float2bfloat16(x - __bfloat162float(hi));
}

// ---------------- PTX helpers (compute_100-safe only) ----------------
__device__ __forceinline__ uint32_t smem_u32(const void* p) {
    uint32_t a;
    asm("{ .reg .u64 t; cvta.to.shared.u64 t, %1; cvt.u32.u64 %0, t; }" : "=r"(a) : "l"(p));
    return a;
}
__device__ __forceinline__ void cp_async16(uint32_t dst, const void* src) {
    asm volatile("cp.async.cg.shared.global [%0], [%1], 16;\n" :: "r"(dst), "l"(src));
}
__device__ __forceinline__ void cp_commit() { asm volatile("cp.async.commit_group;\n"); }
template <int N> __device__ __forceinline__ void cp_waitg() {
    asm volatile("cp.async.wait_group %0;\n" :: "n"(N));
}
__device__ __forceinline__ void ldm_x4(uint32_t& r0, uint32_t& r1, uint32_t& r2, uint32_t& r3,
                                       uint32_t addr) {
    asm volatile("ldmatrix.sync.aligned.m8n8.x4.shared.b16 {%0,%1,%2,%3}, [%4];"
                 : "=r"(r0), "=r"(r1), "=r"(r2), "=r"(r3) : "r"(addr));
}
__device__ __forceinline__ void mma_bf16(float& c0, float& c1, float& c2, float& c3,
                                         uint32_t a0, uint32_t a1, uint32_t a2, uint32_t a3,
                                         uint32_t b0, uint32_t b1) {
    asm volatile("mma.sync.aligned.m16n8k16.row.col.f32.bf16.bf16.f32 "
                 "{%0,%1,%2,%3}, {%4,%5,%6,%7}, {%8,%9}, {%0,%1,%2,%3};"
                 : "+f"(c0), "+f"(c1), "+f"(c2), "+f"(c3)
                 : "r"(a0), "r"(a1), "r"(a2), "r"(a3), "r"(b0), "r"(b1));
}
__device__ __forceinline__ uint32_t sw128(uint32_t bo) { return bo ^ ((bo >> 3) & 0x70); }

// ---------------------------------------------------------------------------
// Init: A" <- split(hn), g_H <- hn, pads <- 0, t=0 x-columns, loss <- 0
// ---------------------------------------------------------------------------
__global__ void k_init(const float* __restrict__ hn, const float* __restrict__ cur_pm,
                       const float* __restrict__ aux) {
    int row = blockIdx.x;
    int tid = threadIdx.x;
    __nv_bfloat16* Ab = g_Abf + (size_t)row * KB3;
    for (int j = tid; j < HID; j += blockDim.x) {
        float x = hn[row * HID + j];
        __nv_bfloat16 hi, lo;
        split_bf(x, hi, lo);
        Ab[j] = hi; Ab[SEC + j] = lo; Ab[2 * SEC + j] = hi;
        g_H[row * HID + j] = x;
    }
    if (tid < 16) Ab[3120 + tid] = __float2bfloat16(0.0f);
    // t=0 x-fill: dec = current_pm25 (i==0 branch of the reference)
    if (tid < 14) {
        float xv = (tid == 0) ? cur_pm[row]
                 : (tid == 13) ? 1.0f
                 : aux[(row * TT + 0) * 12 + (tid - 1)];
        __nv_bfloat16 hi, lo;
        split_bf(xv, hi, lo);
        Ab[1024 + tid] = hi;
        Ab[SEC + 1024 + tid] = lo;
        Ab[2 * SEC + 1024 + tid] = hi;
    }
    if (tid == 0) {
        __nv_bfloat16 z = __float2bfloat16(0.0f);
        for (int s = 0; s < 3; s++) { Ab[s * SEC + 1038] = z; Ab[s * SEC + 1039] = z; }
        if (row == 0) g_loss = 0.0f;
    }
}

// ---------------------------------------------------------------------------
// Build W" bf16 [3072 x 3136]: sections [W_hi | W_hi | W_lo]
// ---------------------------------------------------------------------------
__global__ void k_wbf(const float* __restrict__ W_hh, const float* __restrict__ W_ih,
                      const float* __restrict__ b_ih, const float* __restrict__ b_hh) {
    size_t total = (size_t)H3 * KB3;
    for (size_t idx = (size_t)blockIdx.x * blockDim.x + threadIdx.x; idx < total;
         idx += (size_t)gridDim.x * blockDim.x) {
        int c = (int)(idx / KB3);
        int k = (int)(idx - (size_t)c * KB3);
        __nv_bfloat16 outv;
        if (k >= 3120) {
            outv = __float2bfloat16(0.0f);
        } else {
            int sec = k / SEC;
            int kk = k - sec * SEC;
            float val;
            if (kk < 1024) val = W_hh[c * 1024 + kk];
            else if (kk <= 1036) val = (c < 2048) ? W_ih[c * 13 + (kk - 1024)] : 0.0f;
            else if (kk == 1037) val = (c < 2048) ? (b_ih[c] + b_hh[c]) : b_hh[c];
            else val = 0.0f;
            __nv_bfloat16 hi, lo;
            split_bf(val, hi, lo);
            outv = (sec < 2) ? hi : lo;
        }
        g_Wbf[idx] = outv;
    }
}

// ---------------------------------------------------------------------------
// Precompute aux-part of i_n for ALL steps (fp32, exact same math as before):
//   g_inaux[t][row][j] = b_ih[2048+j] + sum_f aux[row,t,f] * W_ih[(2048+j)*13 + 1 + f]
// grid (TT, BSZ/64); 8 warps x 8 rows each; smem wt[13][1024] conflict-free.
// ---------------------------------------------------------------------------
__global__ void __launch_bounds__(256) k_inaux(const float* __restrict__ aux,
                                               const float* __restrict__ W_ih,
                                               const float* __restrict__ b_ih) {
    extern __shared__ float wt[];  // wt[c*1024 + j]
    int tid = threadIdx.x;
    for (int idx = tid; idx < 13 * HID; idx += 256) {
        int c = idx >> 10, j = idx & 1023;
        wt[idx] = (c == 0) ? b_ih[2048 + j] : W_ih[(2048 + j) * 13 + c];
    }
    __syncthreads();
    int t = blockIdx.x;
    int lane = tid & 31, wid = tid >> 5;
    for (int rr = 0; rr < 8; rr++) {
        int row = blockIdx.y * 64 + wid * 8 + rr;
        float ax[12];
#pragma unroll
        for (int f = 0; f < 12; f++) ax[f] = aux[(row * TT + t) * 12 + f];
        float* out = g_inaux + ((size_t)t * BSZ + row) * HID;
#pragma unroll 2
        for (int j = lane; j < HID; j += 32) {
            float s = wt[j];
#pragma unroll
            for (int f = 0; f < 12; f++) s = fmaf(ax[f], wt[(f + 1) * HID + j], s);
            out[j] = s;
        }
    }
}

// ---------------------------------------------------------------------------
// Tensor-core GEMM via mma.sync: gates[m][n] = sum_k A"[m][k] * W"[n][k]
// 128x128 CTA tile, K-chunks of 64 bf16 (SW128), 3-stage cp.async pipeline
// (96KB smem -> 2 CTAs/SM), ONE __syncthreads per chunk, prefetch distance 2.
// ---------------------------------------------------------------------------
__global__ void __launch_bounds__(256, 2) k_gemm_mma() {
    extern __shared__ char smem[];
    uint32_t sb = smem_u32(smem);
    const int tid = threadIdx.x;
    const int wid = tid >> 5;
    const int lane = tid & 31;
    const int bn = blockIdx.x * 128;  // 24 N-tiles
    const int bm = blockIdx.y * 128;  // 32 M-tiles
    const int wm = wid >> 2;          // 0..1 -> 64-row slab
    const int wn = wid & 3;           // 0..3 -> 32-col slab

    const __nv_bfloat16* Ag = g_Abf + (size_t)bm * KB3;
    const __nv_bfloat16* Wg = g_Wbf + (size_t)bn * KB3;

    float acc[4][4][4];
#pragma unroll
    for (int i = 0; i < 4; i++)
#pragma unroll
        for (int j = 0; j < 4; j++)
#pragma unroll
            for (int v2 = 0; v2 < 4; v2++) acc[i][j][v2] = 0.0f;

    const int rA = (lane & 7) + ((lane >> 3) & 1) * 8;
    const int cA = (lane >> 4) * 16;
    const int rB = lane & 7;
    const int hB = ((lane >> 3) & 1) * 16;
    const int pB = (lane >> 4);

#define FILL(s, c) do {                                                          \
    uint32_t _ab = sb + (uint32_t)(s) * 32768u;                                  \
    uint32_t _bb = _ab + 16384u;                                                 \
    _Pragma("unroll")                                                            \
    for (int q = 0; q < 4; q++) {                                                \
        int i = tid + q * 256;                                                   \
        int row = i >> 3, seg = i & 7;                                           \
        uint32_t bo = (uint32_t)(row * 128 + seg * 16);                          \
        uint32_t sw = sw128(bo);                                                 \
        const char* ga = (const char*)(Ag + (size_t)row * KB3 + (c) * 64) + seg * 16; \
        const char* gb = (const char*)(Wg + (size_t)row * KB3 + (c) * 64) + seg * 16; \
        cp_async16(_ab + sw, ga);                                                \
        cp_async16(_bb + sw, gb);                                                \
    }                                                                            \
} while (0)

    FILL(0, 0); cp_commit();
    FILL(1, 1); cp_commit();

    for (int c = 0; c < CHUNKS; c++) {
        // waitg: chunk c's group complete (groups retire in order); the single
        // barrier publishes chunk c to all warps AND certifies stage (c+2)%3
        // (= (c-1)%3, last read during iter c-1) is reusable.
        if (c + 2 < CHUNKS) {
            cp_waitg<1>();
            __syncthreads();
            FILL((c + 2) % 3, c + 2);
            cp_commit();
        } else if (c + 1 < CHUNKS) {
            cp_waitg<1>();
            __syncthreads();
        } else {
            cp_waitg<0>();
            __syncthreads();
        }

        uint32_t ab = sb + (uint32_t)(c % 3) * 32768u;
        uint32_t bb = ab + 16384u;
#pragma unroll
        for (int kk = 0; kk < 4; kk++) {
            uint32_t a[4][4];
#pragma unroll
            for (int mt = 0; mt < 4; mt++) {
                uint32_t bo = (uint32_t)((wm * 64 + mt * 16 + rA) * 128 + kk * 32 + cA);
                ldm_x4(a[mt][0], a[mt][1], a[mt][2], a[mt][3], ab + sw128(bo));
            }
            uint32_t b[4][2];
#pragma unroll
            for (int ntp = 0; ntp < 2; ntp++) {
                uint32_t bo = (uint32_t)((wn * 32 + (ntp * 2 + pB) * 8 + rB) * 128 + kk * 32 + hB);
                ldm_x4(b[ntp * 2][0], b[ntp * 2][1], b[ntp * 2 + 1][0], b[ntp * 2 + 1][1],
                       bb + sw128(bo));
            }
#pragma unroll
            for (int mt = 0; mt < 4; mt++)
#pragma unroll
                for (int nt = 0; nt < 4; nt++)
                    mma_bf16(acc[mt][nt][0], acc[mt][nt][1], acc[mt][nt][2], acc[mt][nt][3],
                             a[mt][0], a[mt][1], a[mt][2], a[mt][3],
                             b[nt][0], b[nt][1]);
        }
    }
#undef FILL

    int quad = lane >> 2;
    int tig = lane & 3;
#pragma unroll
    for (int mt = 0; mt < 4; mt++) {
        int row0 = bm + wm * 64 + mt * 16 + quad;
#pragma unroll
        for (int nt = 0; nt < 4; nt++) {
            int col = bn + wn * 32 + nt * 8 + tig * 2;
            *(float2*)&g_gates[(size_t)row0 * H3 + col] =
                make_float2(acc[mt][nt][0], acc[mt][nt][1]);
            *(float2*)&g_gates[(size_t)(row0 + 8) * H3 + col] =
                make_float2(acc[mt][nt][2], acc[mt][nt][3]);
        }
    }
}

// ---------------------------------------------------------------------------
// Warp-per-row GRU elementwise + reductions + fused x-fill for step t+1.
// i_n = g_inaux[t][row] + dec * w1.  smem = w1 (4KB) + ew (24KB) -> 28KB.
// ---------------------------------------------------------------------------
__global__ void __launch_bounds__(256) k_gru_w(
    const float* __restrict__ W_ih, const float* __restrict__ emb,
    const float* __restrict__ W_out, const float* __restrict__ b_out,
    const int* __restrict__ st, const float* __restrict__ aux,
    const float* __restrict__ tgt_seq, const float* __restrict__ v,
    float* __restrict__ outp, int t)
{
    extern __shared__ float sh[];
    float* w1 = sh;            // [1024]: W_ih[(2048+j)*13 + 0]  (dec column)
    float* ew = sh + HID;      // j*6: [emb0..emb4 | W_out]
    __shared__ float sloss;
    int tid = threadIdx.x;

    for (int j = tid; j < HID; j += 256) w1[j] = W_ih[(2048 + j) * 13];
    for (int idx = tid; idx < HID * 6; idx += 256) {
        int j = idx / 6, c = idx - j * 6;
        ew[idx] = (c < 5) ? emb[c * HID + j] : W_out[j];
    }
    if (tid == 0) sloss = 0.0f;
    __syncthreads();

    int lane = tid & 31;
    int wid = tid >> 5;
    int row = blockIdx.x * GRU_WARPS + wid;

    const float* gr = g_gates + (size_t)row * H3;
    const float* inx = g_inaux + ((size_t)t * BSZ + row) * HID;
    __nv_bfloat16* Ab = g_Abf + (size_t)row * KB3;
    float* Hrow = g_H + (size_t)row * HID;

    float dec = __bfloat162float(Ab[1024]) + __bfloat162float(Ab[SEC + 1024]);

    float e0 = 0.f, e1 = 0.f, e2 = 0.f, e3 = 0.f, e4 = 0.f, od = 0.f;

#pragma unroll 4
    for (int j = lane; j < HID; j += 32) {
        float r = sigmoid_fast(gr[j]);
        float z = sigmoid_fast(gr[1024 + j]);
        float in_ = fmaf(dec, w1[j], inx[j]);
        float n = tanh_fast(fmaf(r, gr[2048 + j], in_));
        float hp = Hrow[j];
        float h = (1.0f - z) * n + z * hp;
        Hrow[j] = h;
        __nv_bfloat16 hi, lo;
        split_bf(h, hi, lo);
        Ab[j] = hi; Ab[SEC + j] = lo; Ab[2 * SEC + j] = hi;
        const float* e = &ew[j * 6];
        e0 = fmaf(h, e[0], e0);
        e1 = fmaf(h, e[1], e1);
        e2 = fmaf(h, e[2], e2);
        e3 = fmaf(h, e[3], e3);
        e4 = fmaf(h, e[4], e4);
        od = fmaf(h, e[5], od);
    }

    float vals[6] = {e0, e1, e2, e3, e4, od};
#pragma unroll
    for (int s = 16; s > 0; s >>= 1)
#pragma unroll
        for (int vv = 0; vv < 6; vv++)
            vals[vv] += __shfl_down_sync(0xffffffffu, vals[vv], s);

    float o = 0.0f;
    if (lane == 0) {
        float mx = vals[0];
#pragma unroll
        for (int k2 = 1; k2 < 5; k2++) mx = fmaxf(mx, vals[k2]);
        float se = 0.f;
#pragma unroll
        for (int k2 = 0; k2 < 5; k2++) se += __expf(vals[k2] - mx);
        float lse = mx + __logf(se);
        int pos = st[row * TT + t];
        atomicAdd(&sloss, lse - vals[pos]);
        o = vals[5] + b_out[0];
        outp[row * TT + t] = o;
    }
    o = __shfl_sync(0xffffffffu, o, 0);

    // fused x-fill for step t+1
    if (t + 1 < TT && lane < 14) {
        float xv;
        if (lane == 0) {
            float tg = tgt_seq[row * TT + t];
            float m = (tg != 0.0f) ? v[row * TT + t + 1] : 0.0f;
            xv = (m == 1.0f) ? tg : o;
        } else if (lane == 13) {
            xv = 1.0f;
        } else {
            xv = aux[(row * TT + t + 1) * 12 + (lane - 1)];
        }
        __nv_bfloat16 hi, lo;
        split_bf(xv, hi, lo);
        Ab[1024 + lane] = hi;
        Ab[SEC + 1024 + lane] = lo;
        Ab[2 * SEC + 1024 + lane] = hi;
    }

    __syncthreads();
    if (tid == 0) atomicAdd(&g_loss, sloss);
}

// ---------------------------------------------------------------------------
__global__ void k_final(float* outp, int out_size) {
    if (out_size > BSZ * TT)
        outp[BSZ * TT] = g_loss * (1.0f / ((float)BSZ * (float)TT));
}

// ---------------------------------------------------------------------------
extern "C" void kernel_launch(void* const* d_in, const int* in_sizes, int n_in,
                              void* d_out, int out_size) {
    const float* aux    = (const float*)d_in[0];
    const float* cur_pm = (const float*)d_in[1];
    const float* hn     = (const float*)d_in[2];
    const int*   st     = (const int*)  d_in[3];
    const float* tgt    = (const float*)d_in[4];
    const float* v      = (const float*)d_in[5];
    const float* W_ih   = (const float*)d_in[6];
    const float* W_hh   = (const float*)d_in[7];
    const float* b_ih   = (const float*)d_in[8];
    const float* b_hh   = (const float*)d_in[9];
    const float* emb    = (const float*)d_in[10];
    const float* W_out  = (const float*)d_in[11];
    const float* b_out  = (const float*)d_in[12];
    float* outp = (float*)d_out;

    const int gemm_smem  = STAGES * 32768;   // 96 KB -> 2 CTAs/SM
    const int gru_smem   = (HID + HID * 6) * 4;  // 28 KB
    const int inaux_smem = 13 * HID * 4;         // 52 KB
    cudaFuncSetAttribute(k_gru_w, cudaFuncAttributeMaxDynamicSharedMemorySize, gru_smem);
    cudaFuncSetAttribute(k_gemm_mma, cudaFuncAttributeMaxDynamicSharedMemorySize, gemm_smem);
    cudaFuncSetAttribute(k_inaux, cudaFuncAttributeMaxDynamicSharedMemorySize, inaux_smem);

    k_init<<<BSZ, 256>>>(hn, cur_pm, aux);
    k_wbf<<<2048, 256>>>(W_hh, W_ih, b_ih, b_hh);
    {
        dim3 gi(TT, BSZ / 64);
        k_inaux<<<gi, 256, inaux_smem>>>(aux, W_ih, b_ih);
    }

    dim3 gg(H3 / 128, BSZ / 128);
    for (int t = 0; t < TT; t++) {
        k_gemm_mma<<<gg, 256, gemm_smem>>>();
        k_gru_w<<<BSZ / GRU_WARPS, 256, gru_smem>>>(W_ih, emb, W_out, b_out, st,
                                                    aux, tgt, v, outp, t);
    }
    k_final<<<1, 1>>>(outp, out_size);
}